// round 1
// baseline (speedup 1.0000x reference)
#include <cuda_runtime.h>
#include <math.h>

// ---------------- scratch (no allocations allowed) ----------------
__device__ float g_pooled[16 * 64];            // [b][c]
__device__ float g_att[16 * 4];                // [b][k]
__device__ float g_aggb[16 * 64];              // [b][o]
__device__ float g_aggw[16 * 64 * 64 * 9];     // [b][o][c][t], t = dy*3+dx

// ---------------- kernel 1: global average pool ----------------
// grid = 1024 blocks (one per (b,c) plane), block = 256 threads
__global__ void pool_kernel(const float* __restrict__ x) {
    const int plane = blockIdx.x;               // b*64 + c
    const float4* p = (const float4*)(x + (size_t)plane * 65536);
    float s = 0.f;
    for (int i = threadIdx.x; i < 16384; i += 256) {
        float4 v = p[i];
        s += (v.x + v.y) + (v.z + v.w);
    }
    // warp reduce
    #pragma unroll
    for (int off = 16; off > 0; off >>= 1)
        s += __shfl_xor_sync(0xFFFFFFFFu, s, off);
    __shared__ float sm[8];
    const int lane = threadIdx.x & 31, wid = threadIdx.x >> 5;
    if (lane == 0) sm[wid] = s;
    __syncthreads();
    if (threadIdx.x == 0) {
        float t = 0.f;
        #pragma unroll
        for (int w = 0; w < 8; w++) t += sm[w];
        g_pooled[plane] = t * (1.0f / 65536.0f);
    }
}

// ---------------- kernel 2: attention + aggregated bias ----------------
// single block, 64 threads
__global__ void attn_kernel(const float* __restrict__ fc1_w,   // [17,64]
                            const float* __restrict__ fc2_w,   // [4,17]
                            const float* __restrict__ fc2_b,   // [4]
                            const float* __restrict__ bias_k)  // [4,64]
{
    __shared__ float sh[17];
    __shared__ float sl[4];
    const int t = threadIdx.x;
    for (int b = 0; b < 16; b++) {
        if (t < 17) {
            float s = 0.f;
            #pragma unroll
            for (int c = 0; c < 64; c++) s += g_pooled[b * 64 + c] * fc1_w[t * 64 + c];
            sh[t] = (s >= 0.f) ? s : 0.2f * s;   // LeakyReLU(0.2)
        }
        __syncthreads();
        if (t < 4) {
            float s = fc2_b[t];
            #pragma unroll
            for (int j = 0; j < 17; j++) s += sh[j] * fc2_w[t * 17 + j];
            sl[t] = s * (1.0f / 34.0f);          // temperature
        }
        __syncthreads();
        if (t == 0) {
            float m = fmaxf(fmaxf(sl[0], sl[1]), fmaxf(sl[2], sl[3]));
            float e0 = expf(sl[0] - m), e1 = expf(sl[1] - m);
            float e2 = expf(sl[2] - m), e3 = expf(sl[3] - m);
            float inv = 1.0f / (e0 + e1 + e2 + e3);
            sl[0] = e0 * inv; sl[1] = e1 * inv; sl[2] = e2 * inv; sl[3] = e3 * inv;
        }
        __syncthreads();
        if (t < 4) g_att[b * 4 + t] = sl[t];
        if (t < 64) {
            float s = 0.f;
            #pragma unroll
            for (int k = 0; k < 4; k++) s += sl[k] * bias_k[k * 64 + t];
            g_aggb[b * 64 + t] = s;
        }
        __syncthreads();
    }
}

// ---------------- kernel 3: aggregate weights ----------------
// grid = 2304 x 256, one element each: aggw[b][o][c][t] = sum_k att[b,k]*W[k,o,c,t]
__global__ void aggw_kernel(const float* __restrict__ weight) {  // [4,64,64,3,3]
    const int idx = blockIdx.x * 256 + threadIdx.x;
    if (idx >= 16 * 36864) return;
    const int b = idx / 36864;
    const int r = idx - b * 36864;
    const float a0 = g_att[b * 4 + 0], a1 = g_att[b * 4 + 1];
    const float a2 = g_att[b * 4 + 2], a3 = g_att[b * 4 + 3];
    float s = a0 * weight[r]
            + a1 * weight[36864 + r]
            + a2 * weight[2 * 36864 + r]
            + a3 * weight[3 * 36864 + r];
    g_aggw[idx] = s;
}

// ---------------- kernel 4: the 3x3 conv ----------------
// grid = (256 spatial tiles, 4 o-groups, 16 batch), block = 256 threads
// block tile: 16 output channels x 16x16 spatial; thread = (o_local, output row)
__global__ __launch_bounds__(256)
void conv_kernel(const float* __restrict__ x, float* __restrict__ out) {
    const int b   = blockIdx.z;
    const int og  = blockIdx.y;                 // 0..3 -> o0 = og*16
    const int ty  = blockIdx.x >> 4;
    const int tx  = blockIdx.x & 15;
    const int oy0 = ty * 16, ox0 = tx * 16;

    __shared__ float s_in[8 * 18 * 21];         // [c][y(18)][x stride 21]
    __shared__ float s_w[8 * 16 * 9];           // [c][o_local][t]

    const int row = threadIdx.x & 15;           // output row within tile
    const int o   = threadIdx.x >> 4;           // o_local 0..15

    float acc[16];
    #pragma unroll
    for (int j = 0; j < 16; j++) acc[j] = 0.f;

    const float* xb = x + (size_t)b * 64 * 65536;
    const float* wb = g_aggw + (size_t)b * 36864 + (size_t)(og * 16) * 576;

    for (int c0 = 0; c0 < 64; c0 += 8) {
        __syncthreads();
        // stage input tile: 8 channels x 18x18 (with zero halo)
        for (int idx = threadIdx.x; idx < 8 * 324; idx += 256) {
            const int c   = idx / 324;
            const int rem = idx - c * 324;
            const int y   = rem / 18;
            const int xx  = rem - y * 18;
            const int gy  = oy0 + y - 1;
            const int gx  = ox0 + xx - 1;
            float v = 0.f;
            if ((unsigned)gy < 256u && (unsigned)gx < 256u)
                v = xb[(size_t)(c0 + c) * 65536 + gy * 256 + gx];
            s_in[c * 378 + y * 21 + xx] = v;
        }
        // stage weights: 8 c x 16 o x 9
        for (int idx = threadIdx.x; idx < 1152; idx += 256) {
            const int c   = idx / 144;
            const int rem = idx - c * 144;
            const int ol  = rem / 9;
            const int t   = rem - ol * 9;
            s_w[c * 144 + ol * 9 + t] = wb[(size_t)ol * 576 + (size_t)(c0 + c) * 9 + t];
        }
        __syncthreads();

        #pragma unroll
        for (int c = 0; c < 8; c++) {
            float w[9];
            #pragma unroll
            for (int t = 0; t < 9; t++) w[t] = s_w[c * 144 + o * 9 + t];
            const float* ip = &s_in[c * 378 + row * 21];
            #pragma unroll
            for (int dy = 0; dy < 3; dy++) {
                const float* rp = ip + dy * 21;
                float r[18];
                #pragma unroll
                for (int u = 0; u < 18; u++) r[u] = rp[u];
                const float w0 = w[dy * 3], w1 = w[dy * 3 + 1], w2 = w[dy * 3 + 2];
                #pragma unroll
                for (int j = 0; j < 16; j++)
                    acc[j] += r[j] * w0 + r[j + 1] * w1 + r[j + 2] * w2;
            }
        }
    }

    const int oc = og * 16 + o;
    const float bias = g_aggb[b * 64 + oc];
    float* op = out + (((size_t)b * 64 + oc) * 256 + (oy0 + row)) * 256 + ox0;
    #pragma unroll
    for (int j = 0; j < 16; j++) op[j] = acc[j] + bias;
}

// ---------------- launcher ----------------
extern "C" void kernel_launch(void* const* d_in, const int* in_sizes, int n_in,
                              void* d_out, int out_size) {
    const float* x      = (const float*)d_in[0];  // [16,64,256,256]
    const float* fc1_w  = (const float*)d_in[1];  // [17,64]
    const float* fc2_w  = (const float*)d_in[2];  // [4,17]
    const float* fc2_b  = (const float*)d_in[3];  // [4]
    const float* weight = (const float*)d_in[4];  // [4,64,64,3,3]
    const float* bias_k = (const float*)d_in[5];  // [4,64]
    float* out = (float*)d_out;

    pool_kernel<<<1024, 256>>>(x);
    attn_kernel<<<1, 64>>>(fc1_w, fc2_w, fc2_b, bias_k);
    aggw_kernel<<<2304, 256>>>(weight);
    conv_kernel<<<dim3(256, 4, 16), 256>>>(x, out);
}

// round 3
// speedup vs baseline: 3.1328x; 3.1328x over previous
#include <cuda_runtime.h>
#include <cstdint>
#include <math.h>

// ==================== scratch (no allocations allowed) ====================
__device__ float g_pooled[16 * 64];              // [b][c]
__device__ float g_att[16 * 4];                  // [b][k]
__device__ float g_aggb[16 * 64];                // [b][o]
__device__ float g_aggwt[16 * 9 * 64 * 64];      // [b][tap][o][c], tf32-rounded

// ==================== helpers ====================
__device__ __forceinline__ uint32_t f2tf32(float f) {
    uint32_t u;
    asm("cvt.rna.tf32.f32 %0, %1;" : "=r"(u) : "f"(f));
    return u;
}

__device__ __forceinline__ void mma_tf32(float& c0, float& c1, float& c2, float& c3,
                                         uint32_t a0, uint32_t a1, uint32_t a2, uint32_t a3,
                                         uint32_t b0, uint32_t b1) {
    asm volatile(
        "mma.sync.aligned.m16n8k8.row.col.f32.tf32.tf32.f32 "
        "{%0,%1,%2,%3}, {%4,%5,%6,%7}, {%8,%9}, {%0,%1,%2,%3};"
        : "+f"(c0), "+f"(c1), "+f"(c2), "+f"(c3)
        : "r"(a0), "r"(a1), "r"(a2), "r"(a3), "r"(b0), "r"(b1));
}

// ==================== kernel 1: global average pool ====================
__global__ void pool_kernel(const float* __restrict__ x) {
    const int plane = blockIdx.x;               // b*64 + c
    const float4* p = (const float4*)(x + (size_t)plane * 65536);
    float s = 0.f;
    for (int i = threadIdx.x; i < 16384; i += 256) {
        float4 v = p[i];
        s += (v.x + v.y) + (v.z + v.w);
    }
    #pragma unroll
    for (int off = 16; off > 0; off >>= 1)
        s += __shfl_xor_sync(0xFFFFFFFFu, s, off);
    __shared__ float sm[8];
    const int lane = threadIdx.x & 31, wid = threadIdx.x >> 5;
    if (lane == 0) sm[wid] = s;
    __syncthreads();
    if (threadIdx.x == 0) {
        float t = 0.f;
        #pragma unroll
        for (int w = 0; w < 8; w++) t += sm[w];
        g_pooled[plane] = t * (1.0f / 65536.0f);
    }
}

// ==================== kernel 2: attention + aggregated bias ====================
__global__ void attn_kernel(const float* __restrict__ fc1_w, const float* __restrict__ fc2_w,
                            const float* __restrict__ fc2_b, const float* __restrict__ bias_k) {
    __shared__ float sh[17];
    __shared__ float sl[4];
    const int t = threadIdx.x;
    for (int b = 0; b < 16; b++) {
        if (t < 17) {
            float s = 0.f;
            #pragma unroll
            for (int c = 0; c < 64; c++) s += g_pooled[b * 64 + c] * fc1_w[t * 64 + c];
            sh[t] = (s >= 0.f) ? s : 0.2f * s;
        }
        __syncthreads();
        if (t < 4) {
            float s = fc2_b[t];
            #pragma unroll
            for (int j = 0; j < 17; j++) s += sh[j] * fc2_w[t * 17 + j];
            sl[t] = s * (1.0f / 34.0f);
        }
        __syncthreads();
        if (t == 0) {
            float m = fmaxf(fmaxf(sl[0], sl[1]), fmaxf(sl[2], sl[3]));
            float e0 = expf(sl[0] - m), e1 = expf(sl[1] - m);
            float e2 = expf(sl[2] - m), e3 = expf(sl[3] - m);
            float inv = 1.0f / (e0 + e1 + e2 + e3);
            sl[0] = e0 * inv; sl[1] = e1 * inv; sl[2] = e2 * inv; sl[3] = e3 * inv;
        }
        __syncthreads();
        if (t < 4) g_att[b * 4 + t] = sl[t];
        if (t < 64) {
            float s = 0.f;
            #pragma unroll
            for (int k = 0; k < 4; k++) s += sl[k] * bias_k[k * 64 + t];
            g_aggb[b * 64 + t] = s;
        }
        __syncthreads();
    }
}

// ==================== kernel 3: aggregate + transpose weights (tf32-rounded) ==========
// aggwt[b][tap][o][c] = tf32( sum_k att[b,k] * weight[k,o,c,tap] )
__global__ void aggw_kernel(const float* __restrict__ weight) {  // [4,64,64,3,3]
    const int idx = blockIdx.x * 256 + threadIdx.x;   // b*4096 + o*64 + c
    const int b  = idx >> 12;
    const int oc = idx & 4095;
    const float a0 = g_att[b * 4 + 0], a1 = g_att[b * 4 + 1];
    const float a2 = g_att[b * 4 + 2], a3 = g_att[b * 4 + 3];
    const float* w0 = weight + (size_t)oc * 9;
    #pragma unroll
    for (int tap = 0; tap < 9; tap++) {
        float s = a0 * w0[tap]
                + a1 * w0[4096 * 9 + tap]
                + a2 * w0[2 * 4096 * 9 + tap]
                + a3 * w0[3 * 4096 * 9 + tap];
        g_aggwt[((size_t)(b * 9 + tap) << 12) + oc] = __uint_as_float(f2tf32(s));
    }
}

// ==================== kernel 4: conv as tf32 mma.sync implicit GEMM ====================
// CTA: (b, y, 128-wide half row). D[m=128][n=64], K = 18 chunks of 32 (tap x c-half).
// SMEM layout: row stride 36 floats; within each K=8 block column 2p holds k=p,
// column 2p+1 holds k=p+4 (so fragment loads are float2); column index XOR-swizzled
// by ((row & 3) << 3) to cap bank conflicts at 2-way.
#define SWZ(row, col) ((col) ^ (((row) & 3) << 3))

__global__ __launch_bounds__(128, 3)
void conv_kernel(const float* __restrict__ x, float* __restrict__ out) {
    __shared__ float s_A[128 * 36];
    __shared__ float s_B[64 * 36];
    __shared__ float s_bias[64];

    const int b    = blockIdx.z;
    const int y    = blockIdx.y;
    const int x0   = blockIdx.x << 7;
    const int t    = threadIdx.x;
    const int lane = t & 31, w = t >> 5;
    const int g    = lane >> 2, tig = lane & 3;

    if (t < 64) s_bias[t] = g_aggb[b * 64 + t];

    float acc[2][8][4];
    #pragma unroll
    for (int mt = 0; mt < 2; mt++)
        #pragma unroll
        for (int nt = 0; nt < 8; nt++)
            #pragma unroll
            for (int r = 0; r < 4; r++) acc[mt][nt][r] = 0.f;

    const float* xb = x + ((size_t)b << 22);
    const int nB    = t >> 1;          // B staging: row (output channel)
    const int halfB = t & 1;           // B staging: which 16-channel half of chunk

    float aA[32];                      // prefetched A column (32 channels at my gx)
    float aB[16];                      // prefetched B (16 channels for row nB)

    // ---- prefetch helper (chunk i = tap*2 + ch) ----
    auto load_chunk = [&](int i) {
        const int tap = i >> 1;
        const int c0  = (i & 1) << 5;
        const int dy  = tap / 3 - 1;
        const int dx  = tap % 3 - 1;
        const int gy  = y + dy;
        const int gx  = x0 + t + dx;
        const bool ok = ((unsigned)gy < 256u) && ((unsigned)gx < 256u);
        const float* src = xb + ((size_t)c0 << 16) + gy * 256 + gx;
        #pragma unroll
        for (int c = 0; c < 32; c++)
            aA[c] = ok ? __ldg(src + ((size_t)c << 16)) : 0.f;
        const float* wsrc = g_aggwt + (((size_t)(b * 9 + tap)) << 12) + nB * 64 + c0 + halfB * 16;
        #pragma unroll
        for (int j = 0; j < 4; j++) {
            float4 v = *(const float4*)(wsrc + 4 * j);
            aB[4 * j + 0] = v.x; aB[4 * j + 1] = v.y;
            aB[4 * j + 2] = v.z; aB[4 * j + 3] = v.w;
        }
    };

    load_chunk(0);

    #pragma unroll 1
    for (int i = 0; i < 18; i++) {
        __syncthreads();   // previous chunk's MMAs done reading smem

        // ---- STS A: row m=t, 16 float2 (pairs (k=p, k=p+4) per 8-block), tf32-rounded
        {
            float* rowp = s_A + t * 36;
            #pragma unroll
            for (int blk = 0; blk < 4; blk++)
                #pragma unroll
                for (int p = 0; p < 4; p++) {
                    float2 v;
                    v.x = __uint_as_float(f2tf32(aA[8 * blk + p]));
                    v.y = __uint_as_float(f2tf32(aA[8 * blk + p + 4]));
                    *(float2*)(rowp + SWZ(t, 8 * blk + 2 * p)) = v;
                }
        }
        // ---- STS B: row nB, 8 float2 (weights already tf32-rounded)
        {
            float* rowp = s_B + nB * 36;
            #pragma unroll
            for (int blk2 = 0; blk2 < 2; blk2++)
                #pragma unroll
                for (int p = 0; p < 4; p++) {
                    float2 v;
                    v.x = aB[8 * blk2 + p];
                    v.y = aB[8 * blk2 + p + 4];
                    const int col = 8 * (2 * halfB + blk2) + 2 * p;
                    *(float2*)(rowp + SWZ(nB, col)) = v;
                }
        }
        __syncthreads();

        if (i < 17) load_chunk(i + 1);   // LDG overlaps the MMAs below

        // ---- 4 K-steps of m16n8k8 ----
        #pragma unroll
        for (int ks = 0; ks < 4; ks++) {
            uint32_t bf[8][2];
            #pragma unroll
            for (int nt = 0; nt < 8; nt++) {
                const int n = nt * 8 + g;
                float2 bv = *(const float2*)(s_B + n * 36 + SWZ(n, 8 * ks + 2 * tig));
                bf[nt][0] = __float_as_uint(bv.x);
                bf[nt][1] = __float_as_uint(bv.y);
            }
            #pragma unroll
            for (int mt = 0; mt < 2; mt++) {
                const int m = w * 32 + mt * 16 + g;       // (m+8)&3 == m&3 -> same swizzle
                const int col = SWZ(m, 8 * ks + 2 * tig);
                float2 a02 = *(const float2*)(s_A + m * 36 + col);
                float2 a13 = *(const float2*)(s_A + (m + 8) * 36 + col);
                const uint32_t a0 = __float_as_uint(a02.x), a1 = __float_as_uint(a13.x);
                const uint32_t a2 = __float_as_uint(a02.y), a3 = __float_as_uint(a13.y);
                #pragma unroll
                for (int nt = 0; nt < 8; nt++)
                    mma_tf32(acc[mt][nt][0], acc[mt][nt][1], acc[mt][nt][2], acc[mt][nt][3],
                             a0, a1, a2, a3, bf[nt][0], bf[nt][1]);
            }
        }
    }

    // ---- epilogue ----
    const size_t obase = ((size_t)b << 22) + (size_t)y * 256 + x0;
    #pragma unroll
    for (int nt = 0; nt < 8; nt++) {
        const int o0 = nt * 8 + 2 * tig;
        const float bias0 = s_bias[o0], bias1 = s_bias[o0 + 1];
        #pragma unroll
        for (int mt = 0; mt < 2; mt++) {
            const int m = w * 32 + mt * 16 + g;
            float* p0 = out + obase + ((size_t)o0 << 16) + m;
            float* p1 = out + obase + ((size_t)(o0 + 1) << 16) + m;
            p0[0] = acc[mt][nt][0] + bias0;
            p1[0] = acc[mt][nt][1] + bias1;
            p0[8] = acc[mt][nt][2] + bias0;
            p1[8] = acc[mt][nt][3] + bias1;
        }
    }
}

// ==================== launcher ====================
extern "C" void kernel_launch(void* const* d_in, const int* in_sizes, int n_in,
                              void* d_out, int out_size) {
    const float* x      = (const float*)d_in[0];  // [16,64,256,256]
    const float* fc1_w  = (const float*)d_in[1];  // [17,64]
    const float* fc2_w  = (const float*)d_in[2];  // [4,17]
    const float* fc2_b  = (const float*)d_in[3];  // [4]
    const float* weight = (const float*)d_in[4];  // [4,64,64,3,3]
    const float* bias_k = (const float*)d_in[5];  // [4,64]
    float* out = (float*)d_out;

    pool_kernel<<<1024, 256>>>(x);
    attn_kernel<<<1, 64>>>(fc1_w, fc2_w, fc2_b, bias_k);
    aggw_kernel<<<256, 256>>>(weight);
    conv_kernel<<<dim3(2, 256, 16), 128>>>(x, out);
}

// round 4
// speedup vs baseline: 3.7293x; 1.1904x over previous
#include <cuda_runtime.h>
#include <cstdint>
#include <math.h>

// ==================== scratch (no allocations allowed) ====================
__device__ float g_pooled[16 * 64];              // [b][c]
__device__ float g_att[16 * 4];                  // [b][k]
__device__ float g_aggb[16 * 64];                // [b][o]
__device__ float g_aggwt[16 * 9 * 64 * 64];      // [b][tap][o][c], tf32-rounded

// ==================== helpers ====================
__device__ __forceinline__ uint32_t f2tf32(float f) {
    uint32_t u;
    asm("cvt.rna.tf32.f32 %0, %1;" : "=r"(u) : "f"(f));
    return u;
}

__device__ __forceinline__ void mma_tf32(float& c0, float& c1, float& c2, float& c3,
                                         uint32_t a0, uint32_t a1, uint32_t a2, uint32_t a3,
                                         uint32_t b0, uint32_t b1) {
    asm volatile(
        "mma.sync.aligned.m16n8k8.row.col.f32.tf32.tf32.f32 "
        "{%0,%1,%2,%3}, {%4,%5,%6,%7}, {%8,%9}, {%0,%1,%2,%3};"
        : "+f"(c0), "+f"(c1), "+f"(c2), "+f"(c3)
        : "r"(a0), "r"(a1), "r"(a2), "r"(a3), "r"(b0), "r"(b1));
}

// ==================== kernel 1: global average pool ====================
__global__ void pool_kernel(const float* __restrict__ x) {
    const int plane = blockIdx.x;               // b*64 + c
    const float4* p = (const float4*)(x + (size_t)plane * 65536);
    float s = 0.f;
    for (int i = threadIdx.x; i < 16384; i += 256) {
        float4 v = p[i];
        s += (v.x + v.y) + (v.z + v.w);
    }
    #pragma unroll
    for (int off = 16; off > 0; off >>= 1)
        s += __shfl_xor_sync(0xFFFFFFFFu, s, off);
    __shared__ float sm[8];
    const int lane = threadIdx.x & 31, wid = threadIdx.x >> 5;
    if (lane == 0) sm[wid] = s;
    __syncthreads();
    if (threadIdx.x == 0) {
        float t = 0.f;
        #pragma unroll
        for (int w = 0; w < 8; w++) t += sm[w];
        g_pooled[plane] = t * (1.0f / 65536.0f);
    }
}

// ==================== kernel 2: attention + aggregated bias (1 block per b) ====
__global__ void attn_kernel(const float* __restrict__ fc1_w, const float* __restrict__ fc2_w,
                            const float* __restrict__ fc2_b, const float* __restrict__ bias_k) {
    __shared__ float sh[17];
    __shared__ float sl[4];
    const int b = blockIdx.x;
    const int t = threadIdx.x;
    if (t < 17) {
        float s = 0.f;
        #pragma unroll
        for (int c = 0; c < 64; c++) s += g_pooled[b * 64 + c] * fc1_w[t * 64 + c];
        sh[t] = (s >= 0.f) ? s : 0.2f * s;
    }
    __syncthreads();
    if (t < 4) {
        float s = fc2_b[t];
        #pragma unroll
        for (int j = 0; j < 17; j++) s += sh[j] * fc2_w[t * 17 + j];
        sl[t] = s * (1.0f / 34.0f);
    }
    __syncthreads();
    if (t == 0) {
        float m = fmaxf(fmaxf(sl[0], sl[1]), fmaxf(sl[2], sl[3]));
        float e0 = expf(sl[0] - m), e1 = expf(sl[1] - m);
        float e2 = expf(sl[2] - m), e3 = expf(sl[3] - m);
        float inv = 1.0f / (e0 + e1 + e2 + e3);
        sl[0] = e0 * inv; sl[1] = e1 * inv; sl[2] = e2 * inv; sl[3] = e3 * inv;
    }
    __syncthreads();
    if (t < 4) g_att[b * 4 + t] = sl[t];
    if (t < 64) {
        float s = 0.f;
        #pragma unroll
        for (int k = 0; k < 4; k++) s += sl[k] * bias_k[k * 64 + t];
        g_aggb[b * 64 + t] = s;
    }
}

// ==================== kernel 3: aggregate + transpose weights (tf32-rounded) ====
__global__ void aggw_kernel(const float* __restrict__ weight) {  // [4,64,64,3,3]
    const int idx = blockIdx.x * 256 + threadIdx.x;   // b*4096 + o*64 + c
    const int b  = idx >> 12;
    const int oc = idx & 4095;
    const float a0 = g_att[b * 4 + 0], a1 = g_att[b * 4 + 1];
    const float a2 = g_att[b * 4 + 2], a3 = g_att[b * 4 + 3];
    const float* w0 = weight + (size_t)oc * 9;
    #pragma unroll
    for (int tap = 0; tap < 9; tap++) {
        float s = a0 * w0[tap]
                + a1 * w0[4096 * 9 + tap]
                + a2 * w0[2 * 4096 * 9 + tap]
                + a3 * w0[3 * 4096 * 9 + tap];
        g_aggwt[((size_t)(b * 9 + tap) << 12) + oc] = __uint_as_float(f2tf32(s));
    }
}

// ==================== kernel 4: conv, tf32 mma.sync, halo-tile A ====================
// CTA: (b, y, 128-wide half row). D[m=128 x][n=64 o].
// s_A: 32 rows x A_STRIDE; row r (= ks*4 + p) holds channels (ks*8+p, ks*8+p+4)
//      as float2 over xx = 0..129 (gx = x0-1 .. x0+128). Staged once per dy.
// s_B: 32 rows x B_STRIDE; row r holds (w[o][ks*8+p], w[o][ks*8+p+4]) float2 over o.
//      Staged per tap from registers prefetched during the previous tap's MMAs.
#define A_STRIDE 264
#define B_STRIDE 136
#define SMEM_FLOATS (32 * A_STRIDE + 32 * B_STRIDE + 64)

__global__ __launch_bounds__(128, 3)
void conv_kernel(const float* __restrict__ x, float* __restrict__ out) {
    extern __shared__ float smem[];
    float* s_A    = smem;                       // 32*264
    float* s_B    = smem + 32 * A_STRIDE;       // 32*136
    float* s_bias = s_B + 32 * B_STRIDE;        // 64

    const int b    = blockIdx.z;
    const int y    = blockIdx.y;
    const int x0   = blockIdx.x << 7;
    const int t    = threadIdx.x;
    const int lane = t & 31, w = t >> 5;
    const int g    = lane >> 2, tig = lane & 3;

    if (t < 64) s_bias[t] = g_aggb[b * 64 + t];

    float acc[2][8][4];
    #pragma unroll
    for (int mt = 0; mt < 2; mt++)
        #pragma unroll
        for (int nt = 0; nt < 8; nt++)
            #pragma unroll
            for (int r = 0; r < 4; r++) acc[mt][nt][r] = 0.f;

    const float* xb = x + ((size_t)b << 22);

    // ---- B prefetch: thread owns o = t>>1, c-half = (t&1)*32 ----
    float wreg[32];
    const int oB  = t >> 1;
    const int chB = (t & 1) << 5;
    const float* wbase = g_aggwt + ((size_t)(b * 9) << 12) + oB * 64 + chB;

    #pragma unroll
    for (int j = 0; j < 8; j++) {              // load tap 0
        float4 v = *(const float4*)(wbase + 4 * j);
        wreg[4 * j] = v.x; wreg[4 * j + 1] = v.y; wreg[4 * j + 2] = v.z; wreg[4 * j + 3] = v.w;
    }

    #pragma unroll 1
    for (int t9 = 0; t9 < 9; t9++) {
        const int dy = t9 / 3 - 1;
        const int dx = t9 % 3 - 1;

        __syncthreads();    // previous tap's MMAs done reading s_A / s_B

        // ---- stage A once per dy group ----
        if (dx == -1) {
            const int gy  = y + dy;
            const bool oky = (unsigned)gy < 256u;
            const int gx  = x0 + t - 1;                       // xx = t
            const bool ok = oky && ((unsigned)gx < 256u);
            const float* p0 = xb + (size_t)gy * 256 + gx;
            #pragma unroll 4
            for (int r = 0; r < 32; r++) {
                const int c_lo = ((r >> 2) << 3) + (r & 3);
                float2 v = make_float2(0.f, 0.f);
                if (ok) {
                    const float* p = p0 + ((size_t)c_lo << 16);
                    v.x = __uint_as_float(f2tf32(p[0]));
                    v.y = __uint_as_float(f2tf32(p[(size_t)4 << 16]));
                }
                *(float2*)(s_A + r * A_STRIDE + 2 * t) = v;
            }
            if (t < 64) {                                     // xx = 128, 129
                const int r   = t >> 1;
                const int xx2 = 128 + (t & 1);
                const int gx2 = x0 + xx2 - 1;
                const int c_lo = ((r >> 2) << 3) + (r & 3);
                float2 v = make_float2(0.f, 0.f);
                if (oky && (unsigned)gx2 < 256u) {
                    const float* p = xb + ((size_t)c_lo << 16) + (size_t)gy * 256 + gx2;
                    v.x = __uint_as_float(f2tf32(p[0]));
                    v.y = __uint_as_float(f2tf32(p[(size_t)4 << 16]));
                }
                *(float2*)(s_A + r * A_STRIDE + 2 * xx2) = v;
            }
        }

        // ---- STS B for this tap from prefetched regs ----
        #pragma unroll
        for (int bk = 0; bk < 4; bk++)
            #pragma unroll
            for (int p = 0; p < 4; p++) {
                float2 v = make_float2(wreg[bk * 8 + p], wreg[bk * 8 + p + 4]);
                const int rB = ((chB >> 3) + bk) * 4 + p;
                *(float2*)(s_B + rB * B_STRIDE + 2 * oB) = v;
            }
        __syncthreads();

        // ---- prefetch next tap's B (LDG in flight under MMAs) ----
        if (t9 < 8) {
            const float* src = wbase + ((size_t)(t9 + 1) << 12);
            #pragma unroll
            for (int j = 0; j < 8; j++) {
                float4 v = *(const float4*)(src + 4 * j);
                wreg[4 * j] = v.x; wreg[4 * j + 1] = v.y;
                wreg[4 * j + 2] = v.z; wreg[4 * j + 3] = v.w;
            }
        }

        // ---- 8 K-steps of m16n8k8 over this tap ----
        #pragma unroll
        for (int ks = 0; ks < 8; ks++) {
            const float* bRow = s_B + (ks * 4 + tig) * B_STRIDE;
            uint32_t bf[8][2];
            #pragma unroll
            for (int nt = 0; nt < 8; nt++) {
                float2 bv = *(const float2*)(bRow + 2 * (nt * 8 + g));
                bf[nt][0] = __float_as_uint(bv.x);
                bf[nt][1] = __float_as_uint(bv.y);
            }
            const float* aRow = s_A + (ks * 4 + tig) * A_STRIDE;
            #pragma unroll
            for (int mt = 0; mt < 2; mt++) {
                const int m0  = w * 32 + mt * 16 + g;
                const int xxv = m0 + dx + 1;
                float2 a02 = *(const float2*)(aRow + 2 * xxv);
                float2 a13 = *(const float2*)(aRow + 2 * (xxv + 8));
                const uint32_t a0 = __float_as_uint(a02.x), a1 = __float_as_uint(a13.x);
                const uint32_t a2 = __float_as_uint(a02.y), a3 = __float_as_uint(a13.y);
                #pragma unroll
                for (int nt = 0; nt < 8; nt++)
                    mma_tf32(acc[mt][nt][0], acc[mt][nt][1], acc[mt][nt][2], acc[mt][nt][3],
                             a0, a1, a2, a3, bf[nt][0], bf[nt][1]);
            }
        }
    }

    // ---- epilogue ----
    const size_t obase = ((size_t)b << 22) + (size_t)y * 256 + x0;
    #pragma unroll
    for (int nt = 0; nt < 8; nt++) {
        const int o0 = nt * 8 + 2 * tig;
        const float bias0 = s_bias[o0], bias1 = s_bias[o0 + 1];
        #pragma unroll
        for (int mt = 0; mt < 2; mt++) {
            const int m = w * 32 + mt * 16 + g;
            float* p0 = out + obase + ((size_t)o0 << 16) + m;
            float* p1 = out + obase + ((size_t)(o0 + 1) << 16) + m;
            p0[0] = acc[mt][nt][0] + bias0;
            p1[0] = acc[mt][nt][1] + bias1;
            p0[8] = acc[mt][nt][2] + bias0;
            p1[8] = acc[mt][nt][3] + bias1;
        }
    }
}

// ==================== launcher ====================
extern "C" void kernel_launch(void* const* d_in, const int* in_sizes, int n_in,
                              void* d_out, int out_size) {
    const float* x      = (const float*)d_in[0];  // [16,64,256,256]
    const float* fc1_w  = (const float*)d_in[1];  // [17,64]
    const float* fc2_w  = (const float*)d_in[2];  // [4,17]
    const float* fc2_b  = (const float*)d_in[3];  // [4]
    const float* weight = (const float*)d_in[4];  // [4,64,64,3,3]
    const float* bias_k = (const float*)d_in[5];  // [4,64]
    float* out = (float*)d_out;

    const int smem_bytes = SMEM_FLOATS * 4;
    cudaFuncSetAttribute(conv_kernel, cudaFuncAttributeMaxDynamicSharedMemorySize, smem_bytes);

    pool_kernel<<<1024, 256>>>(x);
    attn_kernel<<<16, 64>>>(fc1_w, fc2_w, fc2_b, bias_k);
    aggw_kernel<<<256, 256>>>(weight);
    conv_kernel<<<dim3(2, 256, 16), 128, smem_bytes>>>(x, out);
}

// round 5
// speedup vs baseline: 4.3252x; 1.1598x over previous
#include <cuda_runtime.h>
#include <cstdint>
#include <math.h>

// ==================== scratch (no allocations allowed) ====================
__device__ float g_pooled[16 * 64];               // [b][c]
__device__ float g_att[16 * 4];                   // [b][k]
__device__ float g_aggb[16 * 64];                 // [b][o]
// interleaved fragment layout: [b][tap][r][o][2] where row r=(c>>3)*4+(c&3)
// holds the pair (w[o][c_lo], w[o][c_lo+4]), c_lo=(r>>2)*8+(r&3); tf32-rounded.
__device__ float g_aggwt2[16 * 9 * 32 * 64 * 2];

// ==================== helpers ====================
__device__ __forceinline__ uint32_t f2tf32(float f) {
    uint32_t u;
    asm("cvt.rna.tf32.f32 %0, %1;" : "=r"(u) : "f"(f));
    return u;
}
__device__ __forceinline__ uint32_t smem_u32(const void* p) {
    uint32_t a;
    asm("{ .reg .u64 t; cvta.to.shared.u64 t, %1; cvt.u32.u64 %0, t; }" : "=r"(a) : "l"(p));
    return a;
}
__device__ __forceinline__ void cp_async16(uint32_t dst, const float* src) {
    asm volatile("cp.async.ca.shared.global [%0], [%1], 16;" :: "r"(dst), "l"(src));
}
#define CP_COMMIT() asm volatile("cp.async.commit_group;" ::: "memory")
#define CP_WAIT0()  asm volatile("cp.async.wait_group 0;" ::: "memory")

__device__ __forceinline__ void mma_tf32(float& c0, float& c1, float& c2, float& c3,
                                         uint32_t a0, uint32_t a1, uint32_t a2, uint32_t a3,
                                         uint32_t b0, uint32_t b1) {
    asm volatile(
        "mma.sync.aligned.m16n8k8.row.col.f32.tf32.tf32.f32 "
        "{%0,%1,%2,%3}, {%4,%5,%6,%7}, {%8,%9}, {%0,%1,%2,%3};"
        : "+f"(c0), "+f"(c1), "+f"(c2), "+f"(c3)
        : "r"(a0), "r"(a1), "r"(a2), "r"(a3), "r"(b0), "r"(b1));
}

// ==================== kernel 1: global average pool ====================
__global__ void pool_kernel(const float* __restrict__ x) {
    const int plane = blockIdx.x;               // b*64 + c
    const float4* p = (const float4*)(x + (size_t)plane * 65536);
    float s = 0.f;
    for (int i = threadIdx.x; i < 16384; i += 256) {
        float4 v = p[i];
        s += (v.x + v.y) + (v.z + v.w);
    }
    #pragma unroll
    for (int off = 16; off > 0; off >>= 1)
        s += __shfl_xor_sync(0xFFFFFFFFu, s, off);
    __shared__ float sm[8];
    const int lane = threadIdx.x & 31, wid = threadIdx.x >> 5;
    if (lane == 0) sm[wid] = s;
    __syncthreads();
    if (threadIdx.x == 0) {
        float t = 0.f;
        #pragma unroll
        for (int w = 0; w < 8; w++) t += sm[w];
        g_pooled[plane] = t * (1.0f / 65536.0f);
    }
}

// ==================== kernel 2: attention + aggregated bias (1 block / b) ====
__global__ void attn_kernel(const float* __restrict__ fc1_w, const float* __restrict__ fc2_w,
                            const float* __restrict__ fc2_b, const float* __restrict__ bias_k) {
    __shared__ float sh[17];
    __shared__ float sl[4];
    const int b = blockIdx.x;
    const int t = threadIdx.x;
    if (t < 17) {
        float s = 0.f;
        #pragma unroll
        for (int c = 0; c < 64; c++) s += g_pooled[b * 64 + c] * fc1_w[t * 64 + c];
        sh[t] = (s >= 0.f) ? s : 0.2f * s;
    }
    __syncthreads();
    if (t < 4) {
        float s = fc2_b[t];
        #pragma unroll
        for (int j = 0; j < 17; j++) s += sh[j] * fc2_w[t * 17 + j];
        sl[t] = s * (1.0f / 34.0f);
    }
    __syncthreads();
    if (t == 0) {
        float m = fmaxf(fmaxf(sl[0], sl[1]), fmaxf(sl[2], sl[3]));
        float e0 = expf(sl[0] - m), e1 = expf(sl[1] - m);
        float e2 = expf(sl[2] - m), e3 = expf(sl[3] - m);
        float inv = 1.0f / (e0 + e1 + e2 + e3);
        sl[0] = e0 * inv; sl[1] = e1 * inv; sl[2] = e2 * inv; sl[3] = e3 * inv;
    }
    __syncthreads();
    if (t < 4) g_att[b * 4 + t] = sl[t];
    if (t < 64) {
        float s = 0.f;
        #pragma unroll
        for (int k = 0; k < 4; k++) s += sl[k] * bias_k[k * 64 + t];
        g_aggb[b * 64 + t] = s;
    }
}

// ==================== kernel 3: aggregate weights -> fragment layout ====
__global__ void aggw_kernel(const float* __restrict__ weight) {  // [4,64,64,3,3]
    const int idx = blockIdx.x * 256 + threadIdx.x;   // b*4096 + o*64 + c
    const int b  = idx >> 12;
    const int oc = idx & 4095;
    const int o  = oc >> 6, c = oc & 63;
    const int r    = ((c >> 3) << 2) + (c & 3);
    const int half = (c >> 2) & 1;
    const float a0 = g_att[b * 4 + 0], a1 = g_att[b * 4 + 1];
    const float a2 = g_att[b * 4 + 2], a3 = g_att[b * 4 + 3];
    const float* w0 = weight + (size_t)oc * 9;
    #pragma unroll
    for (int tap = 0; tap < 9; tap++) {
        float s = a0 * w0[tap]
                + a1 * w0[4096 * 9 + tap]
                + a2 * w0[2 * 4096 * 9 + tap]
                + a3 * w0[3 * 4096 * 9 + tap];
        g_aggwt2[((((size_t)(b * 9 + tap) * 32) + r) * 64 + o) * 2 + half] =
            __uint_as_float(f2tf32(s));
    }
}

// ==================== kernel 4: conv, tf32 mma.sync, warp tile 64x64 ====
// CTA = (b, y): full 256-wide output row, n=64. 128 threads / 4 warps.
// s_A: 32 rows x A_STR; row r holds channel pair (c_lo, c_lo+4) as float2
//      over xx = 0..257 (gx = -1..256). Staged once per dy.
// s_B: double-buffered 32 x B_STR, filled by cp.async one tap ahead.
#define A_STR 520
#define B_STR 136
#define SMEM_FLOATS (32 * A_STR + 2 * 32 * B_STR + 64)

__global__ __launch_bounds__(128, 2)
void conv_kernel(const float* __restrict__ x, float* __restrict__ out) {
    extern __shared__ float smem[];
    float* s_A    = smem;                         // 32*520
    float* s_B    = smem + 32 * A_STR;            // 2 * 32*136
    float* s_bias = s_B + 2 * 32 * B_STR;         // 64

    const int y    = blockIdx.x;
    const int b    = blockIdx.y;
    const int t    = threadIdx.x;
    const int lane = t & 31, w = t >> 5;
    const int g    = lane >> 2, tig = lane & 3;

    if (t < 64) s_bias[t] = g_aggb[b * 64 + t];

    float acc[4][8][4];
    #pragma unroll
    for (int mt = 0; mt < 4; mt++)
        #pragma unroll
        for (int nt = 0; nt < 8; nt++)
            #pragma unroll
            for (int r = 0; r < 4; r++) acc[mt][nt][r] = 0.f;

    const float* xb    = x + ((size_t)b << 22);
    const float* wtap0 = g_aggwt2 + (size_t)(b * 9) * 4096;   // 4096 floats per tap
    const uint32_t sB_addr = smem_u32(s_B);

    // prime tap 0 into buffer 0
    {
        #pragma unroll
        for (int j = 0; j < 8; j++) {
            const int i16 = j * 128 + t;                       // 0..1023
            const int r = i16 >> 5, ch = i16 & 31;
            cp_async16(sB_addr + (uint32_t)(r * B_STR * 4 + ch * 16), wtap0 + i16 * 4);
        }
        CP_COMMIT();
    }

    #pragma unroll 1
    for (int t9 = 0; t9 < 9; t9++) {
        const int dy  = t9 / 3 - 1;
        const int dx  = t9 % 3 - 1;
        const int buf = t9 & 1;

        CP_WAIT0();            // B(t9) landed
        __syncthreads();       // prev tap's MMAs done reading s_A / old B buffer

        // ---- stage A once per dy group ----
        if (dx == -1) {
            const int gy   = y + dy;
            const bool oky = (unsigned)gy < 256u;
            #pragma unroll 1
            for (int xx = t; xx < 258; xx += 128) {
                const int gx  = xx - 1;
                const bool ok = oky && ((unsigned)gx < 256u);
                const float* p0 = xb + (size_t)gy * 256 + gx;
                #pragma unroll 8
                for (int r = 0; r < 32; r++) {
                    const int c_lo = ((r >> 2) << 3) + (r & 3);
                    float2 v = make_float2(0.f, 0.f);
                    if (ok) {
                        const float* p = p0 + ((size_t)c_lo << 16);
                        v.x = __uint_as_float(f2tf32(p[0]));
                        v.y = __uint_as_float(f2tf32(p[(size_t)4 << 16]));
                    }
                    *(float2*)(s_A + r * A_STR + 2 * xx) = v;
                }
            }
        }

        // ---- prefetch next tap's B into the other buffer ----
        if (t9 < 8) {
            const float* src = wtap0 + (size_t)(t9 + 1) * 4096;
            const uint32_t dstb = sB_addr + (uint32_t)((buf ^ 1) * 32 * B_STR * 4);
            #pragma unroll
            for (int j = 0; j < 8; j++) {
                const int i16 = j * 128 + t;
                const int r = i16 >> 5, ch = i16 & 31;
                cp_async16(dstb + (uint32_t)(r * B_STR * 4 + ch * 16), src + i16 * 4);
            }
            CP_COMMIT();
        }
        __syncthreads();       // s_A visible

        // ---- 8 K-steps of m16n8k8 ----
        const float* sBb = s_B + buf * (32 * B_STR);
        #pragma unroll
        for (int ks = 0; ks < 8; ks++) {
            const float* aRow = s_A + (ks * 4 + tig) * A_STR;
            float2 a02[4], a13[4];
            #pragma unroll
            for (int mt = 0; mt < 4; mt++) {
                const int xxv = w * 64 + mt * 16 + g + dx + 1;
                a02[mt] = *(const float2*)(aRow + 2 * xxv);
                a13[mt] = *(const float2*)(aRow + 2 * (xxv + 8));
            }
            const float* bRow = sBb + (ks * 4 + tig) * B_STR;
            #pragma unroll
            for (int nt = 0; nt < 8; nt++) {
                float2 bv = *(const float2*)(bRow + 2 * (nt * 8 + g));
                const uint32_t b0 = __float_as_uint(bv.x), b1 = __float_as_uint(bv.y);
                #pragma unroll
                for (int mt = 0; mt < 4; mt++)
                    mma_tf32(acc[mt][nt][0], acc[mt][nt][1], acc[mt][nt][2], acc[mt][nt][3],
                             __float_as_uint(a02[mt].x), __float_as_uint(a13[mt].x),
                             __float_as_uint(a02[mt].y), __float_as_uint(a13[mt].y),
                             b0, b1);
            }
        }
    }

    // ---- epilogue ----
    const size_t obase = ((size_t)b << 22) + (size_t)y * 256;
    #pragma unroll
    for (int nt = 0; nt < 8; nt++) {
        const int o0 = nt * 8 + 2 * tig;
        const float bias0 = s_bias[o0], bias1 = s_bias[o0 + 1];
        #pragma unroll
        for (int mt = 0; mt < 4; mt++) {
            const int m = w * 64 + mt * 16 + g;
            float* p0 = out + obase + ((size_t)o0 << 16) + m;
            float* p1 = out + obase + ((size_t)(o0 + 1) << 16) + m;
            p0[0] = acc[mt][nt][0] + bias0;
            p1[0] = acc[mt][nt][1] + bias1;
            p0[8] = acc[mt][nt][2] + bias0;
            p1[8] = acc[mt][nt][3] + bias1;
        }
    }
}

// ==================== launcher ====================
extern "C" void kernel_launch(void* const* d_in, const int* in_sizes, int n_in,
                              void* d_out, int out_size) {
    const float* x      = (const float*)d_in[0];  // [16,64,256,256]
    const float* fc1_w  = (const float*)d_in[1];  // [17,64]
    const float* fc2_w  = (const float*)d_in[2];  // [4,17]
    const float* fc2_b  = (const float*)d_in[3];  // [4]
    const float* weight = (const float*)d_in[4];  // [4,64,64,3,3]
    const float* bias_k = (const float*)d_in[5];  // [4,64]
    float* out = (float*)d_out;

    const int smem_bytes = SMEM_FLOATS * 4;
    cudaFuncSetAttribute(conv_kernel, cudaFuncAttributeMaxDynamicSharedMemorySize, smem_bytes);

    pool_kernel<<<1024, 256>>>(x);
    attn_kernel<<<16, 64>>>(fc1_w, fc2_w, fc2_b, bias_k);
    aggw_kernel<<<256, 256>>>(weight);
    conv_kernel<<<dim3(256, 16), 128, smem_bytes>>>(x, out);
}

// round 6
// speedup vs baseline: 6.0982x; 1.4099x over previous
#include <cuda_runtime.h>
#include <cstdint>
#include <math.h>

// ==================== scratch (no allocations allowed) ====================
__device__ float g_pooled[16 * 64];               // [b][c]
__device__ float g_att[16 * 4];                   // [b][k]
__device__ float g_aggb[16 * 64];                 // [b][o]
// fragment layout: [b][tap][r][o][2], r=(c>>3)*4+(c&3) holds (w[o][c_lo], w[o][c_lo+4]),
// c_lo=(r>>2)*8+(r&3); tf32-rounded. Rows r 0..15 = channels 0..31, 16..31 = ch 32..63.
__device__ float g_aggwt2[16 * 9 * 32 * 64 * 2];

// ==================== helpers ====================
__device__ __forceinline__ uint32_t f2tf32(float f) {
    uint32_t u;
    asm("cvt.rna.tf32.f32 %0, %1;" : "=r"(u) : "f"(f));
    return u;
}
__device__ __forceinline__ uint32_t smem_u32(const void* p) {
    uint32_t a;
    asm("{ .reg .u64 t; cvta.to.shared.u64 t, %1; cvt.u32.u64 %0, t; }" : "=r"(a) : "l"(p));
    return a;
}
__device__ __forceinline__ void cp_async16(uint32_t dst, const float* src) {
    asm volatile("cp.async.ca.shared.global [%0], [%1], 16;" :: "r"(dst), "l"(src));
}
// zero-fill variant: src_size < 16 pads with zeros (src_size=0 -> all zeros)
__device__ __forceinline__ void cp_async16z(uint32_t dst, const float* src, uint32_t sz) {
    asm volatile("cp.async.ca.shared.global [%0], [%1], 16, %2;" :: "r"(dst), "l"(src), "r"(sz));
}
#define CP_COMMIT() asm volatile("cp.async.commit_group;" ::: "memory")
#define CP_WAIT0()  asm volatile("cp.async.wait_group 0;" ::: "memory")

__device__ __forceinline__ void mma_tf32(float& c0, float& c1, float& c2, float& c3,
                                         uint32_t a0, uint32_t a1, uint32_t a2, uint32_t a3,
                                         uint32_t b0, uint32_t b1) {
    asm volatile(
        "mma.sync.aligned.m16n8k8.row.col.f32.tf32.tf32.f32 "
        "{%0,%1,%2,%3}, {%4,%5,%6,%7}, {%8,%9}, {%0,%1,%2,%3};"
        : "+f"(c0), "+f"(c1), "+f"(c2), "+f"(c3)
        : "r"(a0), "r"(a1), "r"(a2), "r"(a3), "r"(b0), "r"(b1));
}

// ==================== kernel 1: global average pool ====================
__global__ void pool_kernel(const float* __restrict__ x) {
    const int plane = blockIdx.x;               // b*64 + c
    const float4* p = (const float4*)(x + (size_t)plane * 65536);
    float s = 0.f;
    for (int i = threadIdx.x; i < 16384; i += 256) {
        float4 v = p[i];
        s += (v.x + v.y) + (v.z + v.w);
    }
    #pragma unroll
    for (int off = 16; off > 0; off >>= 1)
        s += __shfl_xor_sync(0xFFFFFFFFu, s, off);
    __shared__ float sm[8];
    const int lane = threadIdx.x & 31, wid = threadIdx.x >> 5;
    if (lane == 0) sm[wid] = s;
    __syncthreads();
    if (threadIdx.x == 0) {
        float t = 0.f;
        #pragma unroll
        for (int w = 0; w < 8; w++) t += sm[w];
        g_pooled[plane] = t * (1.0f / 65536.0f);
    }
}

// ==================== kernel 2: attention + aggregated bias (1 block / b) ====
__global__ void attn_kernel(const float* __restrict__ fc1_w, const float* __restrict__ fc2_w,
                            const float* __restrict__ fc2_b, const float* __restrict__ bias_k) {
    __shared__ float sh[17];
    __shared__ float sl[4];
    const int b = blockIdx.x;
    const int t = threadIdx.x;
    if (t < 17) {
        float s = 0.f;
        #pragma unroll
        for (int c = 0; c < 64; c++) s += g_pooled[b * 64 + c] * fc1_w[t * 64 + c];
        sh[t] = (s >= 0.f) ? s : 0.2f * s;
    }
    __syncthreads();
    if (t < 4) {
        float s = fc2_b[t];
        #pragma unroll
        for (int j = 0; j < 17; j++) s += sh[j] * fc2_w[t * 17 + j];
        sl[t] = s * (1.0f / 34.0f);
    }
    __syncthreads();
    if (t == 0) {
        float m = fmaxf(fmaxf(sl[0], sl[1]), fmaxf(sl[2], sl[3]));
        float e0 = expf(sl[0] - m), e1 = expf(sl[1] - m);
        float e2 = expf(sl[2] - m), e3 = expf(sl[3] - m);
        float inv = 1.0f / (e0 + e1 + e2 + e3);
        sl[0] = e0 * inv; sl[1] = e1 * inv; sl[2] = e2 * inv; sl[3] = e3 * inv;
    }
    __syncthreads();
    if (t < 4) g_att[b * 4 + t] = sl[t];
    if (t < 64) {
        float s = 0.f;
        #pragma unroll
        for (int k = 0; k < 4; k++) s += sl[k] * bias_k[k * 64 + t];
        g_aggb[b * 64 + t] = s;
    }
}

// ==================== kernel 3: aggregate weights -> fragment layout ====
__global__ void aggw_kernel(const float* __restrict__ weight) {  // [4,64,64,3,3]
    const int idx = blockIdx.x * 256 + threadIdx.x;   // b*4096 + o*64 + c
    const int b  = idx >> 12;
    const int oc = idx & 4095;
    const int o  = oc >> 6, c = oc & 63;
    const int r    = ((c >> 3) << 2) + (c & 3);
    const int half = (c >> 2) & 1;
    const float a0 = g_att[b * 4 + 0], a1 = g_att[b * 4 + 1];
    const float a2 = g_att[b * 4 + 2], a3 = g_att[b * 4 + 3];
    const float* w0 = weight + (size_t)oc * 9;
    #pragma unroll
    for (int tap = 0; tap < 9; tap++) {
        float s = a0 * w0[tap]
                + a1 * w0[4096 * 9 + tap]
                + a2 * w0[2 * 4096 * 9 + tap]
                + a3 * w0[3 * 4096 * 9 + tap];
        g_aggwt2[((((size_t)(b * 9 + tap) * 32) + r) * 64 + o) * 2 + half] =
            __uint_as_float(f2tf32(s));
    }
}

// ==================== kernel 4: conv, tf32 mma.sync, fully async staging ====
// CTA = (x-half, y, b): m = 128 x-positions, n = 64. 128 threads / 4 warps,
// warp tile 32x64. 18 steps: group = (dy,ch-half) (6), dx within group (3).
// s_A[buf][32 c][136]: planar channel rows, interior gx at float offset gx-x0+4,
//   halo at offsets 3 and 132. stride 136 == 8 (mod 32) -> conflict-free frags.
// s_B[buf][16 r][136]: fragment-pair rows, cp.async straight copy.
#define A_STR 136
#define B_STR 136
#define SMEM_FLOATS (2 * 32 * A_STR + 2 * 16 * B_STR + 64)

__global__ __launch_bounds__(128, 4)
void conv_kernel(const float* __restrict__ x, float* __restrict__ out) {
    extern __shared__ float smem[];
    float* s_A    = smem;                           // 2 * 32*136
    float* s_B    = smem + 2 * 32 * A_STR;          // 2 * 16*136
    float* s_bias = s_B + 2 * 16 * B_STR;           // 64

    const int x0   = blockIdx.x << 7;               // 0 or 128
    const int y    = blockIdx.y;
    const int b    = blockIdx.z;
    const int t    = threadIdx.x;
    const int lane = t & 31, w = t >> 5;
    const int g    = lane >> 2, tig = lane & 3;

    if (t < 64) s_bias[t] = g_aggb[b * 64 + t];

    float acc[2][8][4];
    #pragma unroll
    for (int mt = 0; mt < 2; mt++)
        #pragma unroll
        for (int nt = 0; nt < 8; nt++)
            #pragma unroll
            for (int r = 0; r < 4; r++) acc[mt][nt][r] = 0.f;

    const float* xb    = x + ((size_t)b << 22);
    const float* wtapb = g_aggwt2 + (size_t)(b * 9) * 4096;
    const uint32_t sA_addr = smem_u32(s_A);
    const uint32_t sB_addr = smem_u32(s_B);

    // ---- A group stage (group = dyi*2 + ch): 32 channels of input row y+dyi-1 ----
    auto issueA = [&](int group) {
        const int dyi = group >> 1;
        const int ch  = group & 1;
        const int gy  = y + dyi - 1;
        const bool oky = (unsigned)gy < 256u;
        const int gyc = oky ? gy : 0;
        const uint32_t sz = oky ? 16u : 0u;
        const uint32_t dstb = sA_addr + (uint32_t)((group & 1) * 32 * A_STR * 4);
        const float* srcb = xb + ((size_t)(ch << 5) << 16) + (size_t)gyc * 256 + x0;
        #pragma unroll
        for (int j = 0; j < 8; j++) {
            const int i  = j * 128 + t;             // 0..1023
            const int cc = i >> 5, k16 = i & 31;
            cp_async16z(dstb + (uint32_t)(cc * (A_STR * 4) + 16 + k16 * 16),
                        srcb + ((size_t)cc << 16) + k16 * 4, sz);
        }
        // halo (2 floats per channel) via plain LDG/STS
        if (t < 64) {
            const int cc = t >> 1, side = t & 1;
            const int gx = x0 + (side ? 128 : -1);
            float v = 0.f;
            if (oky && (unsigned)gx < 256u)
                v = __ldg(xb + ((size_t)((ch << 5) + cc) << 16) + (size_t)gy * 256 + gx);
            *(float*)((char*)smem + (dstb - smem_u32(smem)) + (cc * A_STR + (side ? 132 : 3)) * 4) = v;
        }
    };

    // ---- B step stage (step = group*3 + dxi): 16 fragment rows, contiguous copy ----
    auto issueB = [&](int step) {
        const int gidx = step / 3, dxi = step - gidx * 3;
        const int dyi = gidx >> 1, ch = gidx & 1;
        const int tap = dyi * 3 + dxi;
        const float* src = wtapb + (size_t)tap * 4096 + (ch << 11);
        const uint32_t dstb = sB_addr + (uint32_t)((step & 1) * 16 * B_STR * 4);
        #pragma unroll
        for (int j = 0; j < 4; j++) {
            const int i = j * 128 + t;              // 0..511
            const int r = i >> 5, k16 = i & 31;
            cp_async16(dstb + (uint32_t)(r * (B_STR * 4) + k16 * 16), src + i * 4);
        }
    };

    // prologue
    issueA(0);
    issueB(0);
    CP_COMMIT();

    #pragma unroll 1
    for (int s = 0; s < 18; s++) {
        const int gidx = s / 3;
        const int dx   = (s - gidx * 3) - 1;

        CP_WAIT0();
        __syncthreads();

        if (s < 17) {
            issueB(s + 1);
            if (s - gidx * 3 == 2) issueA(gidx + 1);   // last dx of group: prefetch next A
            CP_COMMIT();
        }

        const float* sAb = s_A + (gidx & 1) * (32 * A_STR);
        const float* sBb = s_B + (s & 1) * (16 * B_STR);

        #pragma unroll
        for (int ks = 0; ks < 4; ks++) {
            // B fragments (hoisted before the HMMA burst)
            const float* bRow = sBb + (ks * 4 + tig) * B_STR;
            uint32_t bf[8][2];
            #pragma unroll
            for (int nt = 0; nt < 8; nt++) {
                float2 bv = *(const float2*)(bRow + 2 * (nt * 8 + g));
                bf[nt][0] = __float_as_uint(bv.x);
                bf[nt][1] = __float_as_uint(bv.y);
            }
            // A fragments: rows c = ks*8+tig and +4, col = m + dx + 4
            const float* aRow0 = sAb + (ks * 8 + tig) * A_STR + (w * 32 + g + dx + 4);
            const float* aRow4 = aRow0 + 4 * A_STR;
            #pragma unroll
            for (int mt = 0; mt < 2; mt++) {
                const uint32_t a0 = __float_as_uint(aRow0[mt * 16]);
                const uint32_t a1 = __float_as_uint(aRow0[mt * 16 + 8]);
                const uint32_t a2 = __float_as_uint(aRow4[mt * 16]);
                const uint32_t a3 = __float_as_uint(aRow4[mt * 16 + 8]);
                #pragma unroll
                for (int nt = 0; nt < 8; nt++)
                    mma_tf32(acc[mt][nt][0], acc[mt][nt][1], acc[mt][nt][2], acc[mt][nt][3],
                             a0, a1, a2, a3, bf[nt][0], bf[nt][1]);
            }
        }
    }

    // ---- epilogue ----
    const size_t obase = ((size_t)b << 22) + (size_t)y * 256 + x0;
    #pragma unroll
    for (int nt = 0; nt < 8; nt++) {
        const int o0 = nt * 8 + 2 * tig;
        const float bias0 = s_bias[o0], bias1 = s_bias[o0 + 1];
        #pragma unroll
        for (int mt = 0; mt < 2; mt++) {
            const int m = w * 32 + mt * 16 + g;
            float* p0 = out + obase + ((size_t)o0 << 16) + m;
            float* p1 = out + obase + ((size_t)(o0 + 1) << 16) + m;
            p0[0] = acc[mt][nt][0] + bias0;
            p1[0] = acc[mt][nt][1] + bias1;
            p0[8] = acc[mt][nt][2] + bias0;
            p1[8] = acc[mt][nt][3] + bias1;
        }
    }
}

// ==================== launcher ====================
extern "C" void kernel_launch(void* const* d_in, const int* in_sizes, int n_in,
                              void* d_out, int out_size) {
    const float* x      = (const float*)d_in[0];  // [16,64,256,256]
    const float* fc1_w  = (const float*)d_in[1];  // [17,64]
    const float* fc2_w  = (const float*)d_in[2];  // [4,17]
    const float* fc2_b  = (const float*)d_in[3];  // [4]
    const float* weight = (const float*)d_in[4];  // [4,64,64,3,3]
    const float* bias_k = (const float*)d_in[5];  // [4,64]
    float* out = (float*)d_out;

    const int smem_bytes = SMEM_FLOATS * 4;
    cudaFuncSetAttribute(conv_kernel, cudaFuncAttributeMaxDynamicSharedMemorySize, smem_bytes);

    pool_kernel<<<1024, 256>>>(x);
    attn_kernel<<<16, 64>>>(fc1_w, fc2_w, fc2_b, bias_k);
    aggw_kernel<<<256, 256>>>(weight);
    conv_kernel<<<dim3(2, 256, 16), 128, smem_bytes>>>(x, out);
}

// round 7
// speedup vs baseline: 6.1867x; 1.0145x over previous
#include <cuda_runtime.h>
#include <cstdint>
#include <math.h>

// ==================== scratch (no allocations allowed) ====================
__device__ float g_pooled[16 * 64];               // [b][c]
__device__ float g_att[16 * 4];                   // [b][k]
__device__ float g_aggb[16 * 64];                 // [b][o]
// fragment layout: [b][tap][r][o][2], r=(c>>3)*4+(c&3) holds (w[o][c_lo], w[o][c_lo+4]),
// c_lo=(r>>2)*8+(r&3); tf32-rounded.
__device__ float g_aggwt2[16 * 9 * 32 * 64 * 2];

// ==================== helpers ====================
__device__ __forceinline__ uint32_t f2tf32(float f) {
    uint32_t u;
    asm("cvt.rna.tf32.f32 %0, %1;" : "=r"(u) : "f"(f));
    return u;
}
__device__ __forceinline__ uint32_t smem_u32(const void* p) {
    uint32_t a;
    asm("{ .reg .u64 t; cvta.to.shared.u64 t, %1; cvt.u32.u64 %0, t; }" : "=r"(a) : "l"(p));
    return a;
}
__device__ __forceinline__ void cp_async16(uint32_t dst, const float* src) {
    asm volatile("cp.async.ca.shared.global [%0], [%1], 16;" :: "r"(dst), "l"(src));
}
__device__ __forceinline__ void cp_async16z(uint32_t dst, const float* src, uint32_t sz) {
    asm volatile("cp.async.ca.shared.global [%0], [%1], 16, %2;" :: "r"(dst), "l"(src), "r"(sz));
}
#define CP_COMMIT() asm volatile("cp.async.commit_group;" ::: "memory")
#define CP_WAIT0()  asm volatile("cp.async.wait_group 0;" ::: "memory")

__device__ __forceinline__ void mma_tf32(float& c0, float& c1, float& c2, float& c3,
                                         uint32_t a0, uint32_t a1, uint32_t a2, uint32_t a3,
                                         uint32_t b0, uint32_t b1) {
    asm volatile(
        "mma.sync.aligned.m16n8k8.row.col.f32.tf32.tf32.f32 "
        "{%0,%1,%2,%3}, {%4,%5,%6,%7}, {%8,%9}, {%0,%1,%2,%3};"
        : "+f"(c0), "+f"(c1), "+f"(c2), "+f"(c3)
        : "r"(a0), "r"(a1), "r"(a2), "r"(a3), "r"(b0), "r"(b1));
}

// ==================== kernel 1: global average pool ====================
__global__ void pool_kernel(const float* __restrict__ x) {
    const int plane = blockIdx.x;               // b*64 + c
    const float4* p = (const float4*)(x + (size_t)plane * 65536);
    float s = 0.f;
    for (int i = threadIdx.x; i < 16384; i += 256) {
        float4 v = p[i];
        s += (v.x + v.y) + (v.z + v.w);
    }
    #pragma unroll
    for (int off = 16; off > 0; off >>= 1)
        s += __shfl_xor_sync(0xFFFFFFFFu, s, off);
    __shared__ float sm[8];
    const int lane = threadIdx.x & 31, wid = threadIdx.x >> 5;
    if (lane == 0) sm[wid] = s;
    __syncthreads();
    if (threadIdx.x == 0) {
        float t = 0.f;
        #pragma unroll
        for (int w = 0; w < 8; w++) t += sm[w];
        g_pooled[plane] = t * (1.0f / 65536.0f);
    }
}

// ==================== kernel 2: attention + aggregated bias (1 block / b) ====
__global__ void attn_kernel(const float* __restrict__ fc1_w, const float* __restrict__ fc2_w,
                            const float* __restrict__ fc2_b, const float* __restrict__ bias_k) {
    __shared__ float sh[17];
    __shared__ float sl[4];
    const int b = blockIdx.x;
    const int t = threadIdx.x;
    if (t < 17) {
        float s = 0.f;
        #pragma unroll
        for (int c = 0; c < 64; c++) s += g_pooled[b * 64 + c] * fc1_w[t * 64 + c];
        sh[t] = (s >= 0.f) ? s : 0.2f * s;
    }
    __syncthreads();
    if (t < 4) {
        float s = fc2_b[t];
        #pragma unroll
        for (int j = 0; j < 17; j++) s += sh[j] * fc2_w[t * 17 + j];
        sl[t] = s * (1.0f / 34.0f);
    }
    __syncthreads();
    if (t == 0) {
        float m = fmaxf(fmaxf(sl[0], sl[1]), fmaxf(sl[2], sl[3]));
        float e0 = expf(sl[0] - m), e1 = expf(sl[1] - m);
        float e2 = expf(sl[2] - m), e3 = expf(sl[3] - m);
        float inv = 1.0f / (e0 + e1 + e2 + e3);
        sl[0] = e0 * inv; sl[1] = e1 * inv; sl[2] = e2 * inv; sl[3] = e3 * inv;
    }
    __syncthreads();
    if (t < 4) g_att[b * 4 + t] = sl[t];
    if (t < 64) {
        float s = 0.f;
        #pragma unroll
        for (int k = 0; k < 4; k++) s += sl[k] * bias_k[k * 64 + t];
        g_aggb[b * 64 + t] = s;
    }
}

// ==================== kernel 3: aggregate weights -> fragment layout ====
__global__ void aggw_kernel(const float* __restrict__ weight) {  // [4,64,64,3,3]
    const int idx = blockIdx.x * 256 + threadIdx.x;   // b*4096 + o*64 + c
    const int b  = idx >> 12;
    const int oc = idx & 4095;
    const int o  = oc >> 6, c = oc & 63;
    const int r    = ((c >> 3) << 2) + (c & 3);
    const int half = (c >> 2) & 1;
    const float a0 = g_att[b * 4 + 0], a1 = g_att[b * 4 + 1];
    const float a2 = g_att[b * 4 + 2], a3 = g_att[b * 4 + 3];
    const float* w0 = weight + (size_t)oc * 9;
    #pragma unroll
    for (int tap = 0; tap < 9; tap++) {
        float s = a0 * w0[tap]
                + a1 * w0[4096 * 9 + tap]
                + a2 * w0[2 * 4096 * 9 + tap]
                + a3 * w0[3 * 4096 * 9 + tap];
        g_aggwt2[((((size_t)(b * 9 + tap) * 32) + r) * 64 + o) * 2 + half] =
            __uint_as_float(f2tf32(s));
    }
}

// ==================== kernel 4: conv, tf32 mma.sync, warp tile 64x64 ====
// CTA = (y, b): full 256-wide output row, n = 64. 128 threads / 4 warps.
// s_A (single buffer): 32 channel rows x A_STR(264); interior gx at col gx+4,
//   halo cols 3 (gx=-1) and 260 (gx=256). Restaged per group (dy, ch-half).
// s_B (double buffer): 16 fragment rows x 136 per (tap, ch-half) step.
#define A_STR 264
#define B_STR 136
#define SMEM_FLOATS (32 * A_STR + 2 * 16 * B_STR + 64)

__global__ __launch_bounds__(128, 3)
void conv_kernel(const float* __restrict__ x, float* __restrict__ out) {
    extern __shared__ float smem[];
    float* s_A    = smem;                           // 32*264
    float* s_B    = smem + 32 * A_STR;              // 2 * 16*136
    float* s_bias = s_B + 2 * 16 * B_STR;           // 64

    const int y    = blockIdx.x;
    const int b    = blockIdx.y;
    const int t    = threadIdx.x;
    const int lane = t & 31, w = t >> 5;
    const int g    = lane >> 2, tig = lane & 3;

    if (t < 64) s_bias[t] = g_aggb[b * 64 + t];

    float acc[4][8][4];
    #pragma unroll
    for (int mt = 0; mt < 4; mt++)
        #pragma unroll
        for (int nt = 0; nt < 8; nt++)
            #pragma unroll
            for (int r = 0; r < 4; r++) acc[mt][nt][r] = 0.f;

    const float* xb    = x + ((size_t)b << 22);
    const float* wtapb = g_aggwt2 + (size_t)(b * 9) * 4096;
    const uint32_t sA_addr = smem_u32(s_A);
    const uint32_t sB_addr = smem_u32(s_B);

    // ---- A stage for group = dyi*2 + ch: 32 channels of input row y+dyi-1 ----
    auto issueA = [&](int group) {
        const int dyi = group >> 1;
        const int ch  = group & 1;
        const int gy  = y + dyi - 1;
        const bool oky = (unsigned)gy < 256u;
        const int gyc = oky ? gy : 0;
        const uint32_t sz = oky ? 16u : 0u;
        const float* srcb = xb + ((size_t)(ch << 5) << 16) + (size_t)gyc * 256;
        #pragma unroll
        for (int j = 0; j < 16; j++) {
            const int i   = j * 128 + t;            // 0..2047
            const int cc  = i >> 6, k16 = i & 63;
            cp_async16z(sA_addr + (uint32_t)(cc * (A_STR * 4) + 16 + k16 * 16),
                        srcb + ((size_t)cc << 16) + k16 * 4, sz);
        }
        if (t < 64) {                               // halo, 2 floats per channel
            const int cc = t >> 1, side = t & 1;
            const int gx = side ? 256 : -1;
            float v = 0.f;
            if (oky && (unsigned)gx < 256u)
                v = __ldg(xb + ((size_t)((ch << 5) + cc) << 16) + (size_t)gy * 256 + gx);
            s_A[cc * A_STR + (side ? 260 : 3)] = v;
        }
    };

    // ---- B stage for step s: (tap, ch-half) fragment rows, contiguous copy ----
    auto issueB = [&](int step) {
        const int gidx = step / 3, dxi = step - gidx * 3;
        const int tap  = (gidx >> 1) * 3 + dxi;
        const int ch   = gidx & 1;
        const float* src = wtapb + (size_t)tap * 4096 + (ch << 11);
        const uint32_t dstb = sB_addr + (uint32_t)((step & 1) * 16 * B_STR * 4);
        #pragma unroll
        for (int j = 0; j < 4; j++) {
            const int i = j * 128 + t;              // 0..511
            const int r = i >> 5, k16 = i & 31;
            cp_async16(dstb + (uint32_t)(r * (B_STR * 4) + k16 * 16), src + i * 4);
        }
    };

    // prologue
    issueA(0);
    issueB(0);
    CP_COMMIT();

    #pragma unroll 1
    for (int s = 0; s < 18; s++) {
        const int gidx = s / 3;
        const int dxi  = s - gidx * 3;
        const int dx   = dxi - 1;
        const bool lastOfGroup = (dxi == 2);

        CP_WAIT0();
        __syncthreads();

        // overlap next B copy with this step's MMAs (A buffer untouched)
        if (s < 17 && !lastOfGroup) {
            issueB(s + 1);
            CP_COMMIT();
        }

        const float* sBb = s_B + (s & 1) * (16 * B_STR);
        const int colbase = w * 64 + g + dx + 4;

        #pragma unroll
        for (int ks = 0; ks < 4; ks++) {
            const float* aRow0 = s_A + (ks * 8 + tig) * A_STR + colbase;
            const float* aRow4 = aRow0 + 4 * A_STR;
            uint32_t a[4][4];
            #pragma unroll
            for (int mt = 0; mt < 4; mt++) {
                a[mt][0] = __float_as_uint(aRow0[mt * 16]);
                a[mt][1] = __float_as_uint(aRow0[mt * 16 + 8]);
                a[mt][2] = __float_as_uint(aRow4[mt * 16]);
                a[mt][3] = __float_as_uint(aRow4[mt * 16 + 8]);
            }
            const float* bRow = sBb + (ks * 4 + tig) * B_STR;
            #pragma unroll
            for (int nt = 0; nt < 8; nt++) {
                float2 bv = *(const float2*)(bRow + 2 * (nt * 8 + g));
                const uint32_t b0 = __float_as_uint(bv.x), b1 = __float_as_uint(bv.y);
                #pragma unroll
                for (int mt = 0; mt < 4; mt++)
                    mma_tf32(acc[mt][nt][0], acc[mt][nt][1], acc[mt][nt][2], acc[mt][nt][3],
                             a[mt][0], a[mt][1], a[mt][2], a[mt][3], b0, b1);
            }
        }

        // group boundary: restage A (after all warps' MMAs) + next B
        if (s < 17 && lastOfGroup) {
            __syncthreads();
            issueA(gidx + 1);
            issueB(s + 1);
            CP_COMMIT();
        }
    }

    // ---- epilogue ----
    const size_t obase = ((size_t)b << 22) + (size_t)y * 256;
    #pragma unroll
    for (int nt = 0; nt < 8; nt++) {
        const int o0 = nt * 8 + 2 * tig;
        const float bias0 = s_bias[o0], bias1 = s_bias[o0 + 1];
        #pragma unroll
        for (int mt = 0; mt < 4; mt++) {
            const int m = w * 64 + mt * 16 + g;
            float* p0 = out + obase + ((size_t)o0 << 16) + m;
            float* p1 = out + obase + ((size_t)(o0 + 1) << 16) + m;
            p0[0] = acc[mt][nt][0] + bias0;
            p1[0] = acc[mt][nt][1] + bias1;
            p0[8] = acc[mt][nt][2] + bias0;
            p1[8] = acc[mt][nt][3] + bias1;
        }
    }
}

// ==================== launcher ====================
extern "C" void kernel_launch(void* const* d_in, const int* in_sizes, int n_in,
                              void* d_out, int out_size) {
    const float* x      = (const float*)d_in[0];  // [16,64,256,256]
    const float* fc1_w  = (const float*)d_in[1];  // [17,64]
    const float* fc2_w  = (const float*)d_in[2];  // [4,17]
    const float* fc2_b  = (const float*)d_in[3];  // [4]
    const float* weight = (const float*)d_in[4];  // [4,64,64,3,3]
    const float* bias_k = (const float*)d_in[5];  // [4,64]
    float* out = (float*)d_out;

    const int smem_bytes = SMEM_FLOATS * 4;
    cudaFuncSetAttribute(conv_kernel, cudaFuncAttributeMaxDynamicSharedMemorySize, smem_bytes);

    pool_kernel<<<1024, 256>>>(x);
    attn_kernel<<<16, 64>>>(fc1_w, fc2_w, fc2_b, bias_k);
    aggw_kernel<<<256, 256>>>(weight);
    conv_kernel<<<dim3(256, 16), 128, smem_bytes>>>(x, out);
}

// round 8
// speedup vs baseline: 6.6997x; 1.0829x over previous
#include <cuda_runtime.h>
#include <cstdint>
#include <math.h>

// ==================== scratch (no allocations allowed) ====================
__device__ float g_pooled[16 * 64];               // [b][c]
__device__ float g_att[16 * 4];                   // [b][k]
__device__ float g_aggb[16 * 64];                 // [b][o]
// fragment layout: [b][tap][r][o][2], r=(c>>3)*4+(c&3) holds (w[o][c_lo], w[o][c_lo+4]),
// c_lo=(r>>2)*8+(r&3); tf32-rounded.
__device__ float g_aggwt2[16 * 9 * 32 * 64 * 2];

// ==================== helpers ====================
__device__ __forceinline__ uint32_t f2tf32(float f) {
    uint32_t u;
    asm("cvt.rna.tf32.f32 %0, %1;" : "=r"(u) : "f"(f));
    return u;
}
__device__ __forceinline__ uint32_t smem_u32(const void* p) {
    uint32_t a;
    asm("{ .reg .u64 t; cvta.to.shared.u64 t, %1; cvt.u32.u64 %0, t; }" : "=r"(a) : "l"(p));
    return a;
}
__device__ __forceinline__ void cp_async16(uint32_t dst, const float* src) {
    asm volatile("cp.async.ca.shared.global [%0], [%1], 16;" :: "r"(dst), "l"(src));
}
__device__ __forceinline__ void cp_async16z(uint32_t dst, const float* src, uint32_t sz) {
    asm volatile("cp.async.ca.shared.global [%0], [%1], 16, %2;" :: "r"(dst), "l"(src), "r"(sz));
}
#define CP_COMMIT() asm volatile("cp.async.commit_group;" ::: "memory")
#define CP_WAIT0()  asm volatile("cp.async.wait_group 0;" ::: "memory")

__device__ __forceinline__ void mma_tf32(float& c0, float& c1, float& c2, float& c3,
                                         uint32_t a0, uint32_t a1, uint32_t a2, uint32_t a3,
                                         uint32_t b0, uint32_t b1) {
    asm volatile(
        "mma.sync.aligned.m16n8k8.row.col.f32.tf32.tf32.f32 "
        "{%0,%1,%2,%3}, {%4,%5,%6,%7}, {%8,%9}, {%0,%1,%2,%3};"
        : "+f"(c0), "+f"(c1), "+f"(c2), "+f"(c3)
        : "r"(a0), "r"(a1), "r"(a2), "r"(a3), "r"(b0), "r"(b1));
}

// ==================== kernel 1: global average pool ====================
__global__ void pool_kernel(const float* __restrict__ x) {
    const int plane = blockIdx.x;               // b*64 + c
    const float4* p = (const float4*)(x + (size_t)plane * 65536);
    float s = 0.f;
    for (int i = threadIdx.x; i < 16384; i += 256) {
        float4 v = p[i];
        s += (v.x + v.y) + (v.z + v.w);
    }
    #pragma unroll
    for (int off = 16; off > 0; off >>= 1)
        s += __shfl_xor_sync(0xFFFFFFFFu, s, off);
    __shared__ float sm[8];
    const int lane = threadIdx.x & 31, wid = threadIdx.x >> 5;
    if (lane == 0) sm[wid] = s;
    __syncthreads();
    if (threadIdx.x == 0) {
        float t = 0.f;
        #pragma unroll
        for (int w = 0; w < 8; w++) t += sm[w];
        g_pooled[plane] = t * (1.0f / 65536.0f);
    }
}

// ==================== kernel 2: attention + aggregated bias (1 block / b) ====
__global__ void attn_kernel(const float* __restrict__ fc1_w, const float* __restrict__ fc2_w,
                            const float* __restrict__ fc2_b, const float* __restrict__ bias_k) {
    __shared__ float sh[17];
    __shared__ float sl[4];
    const int b = blockIdx.x;
    const int t = threadIdx.x;
    if (t < 17) {
        float s = 0.f;
        #pragma unroll
        for (int c = 0; c < 64; c++) s += g_pooled[b * 64 + c] * fc1_w[t * 64 + c];
        sh[t] = (s >= 0.f) ? s : 0.2f * s;
    }
    __syncthreads();
    if (t < 4) {
        float s = fc2_b[t];
        #pragma unroll
        for (int j = 0; j < 17; j++) s += sh[j] * fc2_w[t * 17 + j];
        sl[t] = s * (1.0f / 34.0f);
    }
    __syncthreads();
    if (t == 0) {
        float m = fmaxf(fmaxf(sl[0], sl[1]), fmaxf(sl[2], sl[3]));
        float e0 = expf(sl[0] - m), e1 = expf(sl[1] - m);
        float e2 = expf(sl[2] - m), e3 = expf(sl[3] - m);
        float inv = 1.0f / (e0 + e1 + e2 + e3);
        sl[0] = e0 * inv; sl[1] = e1 * inv; sl[2] = e2 * inv; sl[3] = e3 * inv;
    }
    __syncthreads();
    if (t < 4) g_att[b * 4 + t] = sl[t];
    if (t < 64) {
        float s = 0.f;
        #pragma unroll
        for (int k = 0; k < 4; k++) s += sl[k] * bias_k[k * 64 + t];
        g_aggb[b * 64 + t] = s;
    }
}

// ==================== kernel 3: aggregate weights -> fragment layout ====
__global__ void aggw_kernel(const float* __restrict__ weight) {  // [4,64,64,3,3]
    const int idx = blockIdx.x * 256 + threadIdx.x;   // b*4096 + o*64 + c
    const int b  = idx >> 12;
    const int oc = idx & 4095;
    const int o  = oc >> 6, c = oc & 63;
    const int r    = ((c >> 3) << 2) + (c & 3);
    const int half = (c >> 2) & 1;
    const float a0 = g_att[b * 4 + 0], a1 = g_att[b * 4 + 1];
    const float a2 = g_att[b * 4 + 2], a3 = g_att[b * 4 + 3];
    const float* w0 = weight + (size_t)oc * 9;
    #pragma unroll
    for (int tap = 0; tap < 9; tap++) {
        float s = a0 * w0[tap]
                + a1 * w0[4096 * 9 + tap]
                + a2 * w0[2 * 4096 * 9 + tap]
                + a3 * w0[3 * 4096 * 9 + tap];
        g_aggwt2[((((size_t)(b * 9 + tap) * 32) + r) * 64 + o) * 2 + half] =
            __uint_as_float(f2tf32(s));
    }
}

// ==================== kernel 4: conv, tf32 mma.sync, fully pipelined ====
// CTA = (y, b): full 256-wide output row, n = 64. 128 threads / 4 warps,
// warp tile 64x64. 18 steps = 6 groups (dy, ch-half) x 3 dx.
// s_A double buffer [2][32 c][A_STR]: interior gx at col gx+4, halo cols 3 / 260.
//   A(g+1) issued during the FIRST dx-step of group g (into the idle buffer).
// s_B double buffer [2][16 r][B_STR]: issued one step ahead, always before MMAs.
#define A_STR 264
#define B_STR 136
#define SMEM_FLOATS (2 * 32 * A_STR + 2 * 16 * B_STR + 64)

__global__ __launch_bounds__(128, 2)
void conv_kernel(const float* __restrict__ x, float* __restrict__ out) {
    extern __shared__ float smem[];
    float* s_A    = smem;                           // 2 * 32*264
    float* s_B    = smem + 2 * 32 * A_STR;          // 2 * 16*136
    float* s_bias = s_B + 2 * 16 * B_STR;           // 64

    const int y    = blockIdx.x;
    const int b    = blockIdx.y;
    const int t    = threadIdx.x;
    const int lane = t & 31, w = t >> 5;
    const int g    = lane >> 2, tig = lane & 3;

    if (t < 64) s_bias[t] = g_aggb[b * 64 + t];

    float acc[4][8][4];
    #pragma unroll
    for (int mt = 0; mt < 4; mt++)
        #pragma unroll
        for (int nt = 0; nt < 8; nt++)
            #pragma unroll
            for (int r = 0; r < 4; r++) acc[mt][nt][r] = 0.f;

    const float* xb    = x + ((size_t)b << 22);
    const float* wtapb = g_aggwt2 + (size_t)(b * 9) * 4096;
    const uint32_t sA_addr = smem_u32(s_A);
    const uint32_t sB_addr = smem_u32(s_B);

    // ---- A stage for group = dyi*2 + ch (buffer = group&1) ----
    auto issueA = [&](int group) {
        const int dyi = group >> 1;
        const int ch  = group & 1;
        const int gy  = y + dyi - 1;
        const bool oky = (unsigned)gy < 256u;
        const int gyc = oky ? gy : 0;
        const uint32_t sz = oky ? 16u : 0u;
        const uint32_t dstA = sA_addr + (uint32_t)((group & 1) * 32 * A_STR * 4);
        const float* srcb = xb + ((size_t)(ch << 5) << 16) + (size_t)gyc * 256;
        #pragma unroll
        for (int j = 0; j < 16; j++) {
            const int i   = j * 128 + t;            // 0..2047
            const int cc  = i >> 6, k16 = i & 63;
            cp_async16z(dstA + (uint32_t)(cc * (A_STR * 4) + 16 + k16 * 16),
                        srcb + ((size_t)cc << 16) + k16 * 4, sz);
        }
        if (t < 64) {                               // halo, 2 floats per channel
            const int cc = t >> 1, side = t & 1;
            const int gx = side ? 256 : -1;
            float v = 0.f;
            if (oky && (unsigned)gx < 256u)
                v = __ldg(xb + ((size_t)((ch << 5) + cc) << 16) + (size_t)gy * 256 + gx);
            s_A[(group & 1) * 32 * A_STR + cc * A_STR + (side ? 260 : 3)] = v;
        }
    };

    // ---- B stage for step s: (tap, ch-half) fragment rows, contiguous copy ----
    auto issueB = [&](int step) {
        const int gidx = step / 3, dxi = step - gidx * 3;
        const int tap  = (gidx >> 1) * 3 + dxi;
        const int ch   = gidx & 1;
        const float* src = wtapb + (size_t)tap * 4096 + (ch << 11);
        const uint32_t dstb = sB_addr + (uint32_t)((step & 1) * 16 * B_STR * 4);
        #pragma unroll
        for (int j = 0; j < 4; j++) {
            const int i = j * 128 + t;              // 0..511
            const int r = i >> 5, k16 = i & 31;
            cp_async16(dstb + (uint32_t)(r * (B_STR * 4) + k16 * 16), src + i * 4);
        }
    };

    // prologue
    issueA(0);
    issueB(0);
    CP_COMMIT();

    #pragma unroll 1
    for (int s = 0; s < 18; s++) {
        const int gidx = s / 3;
        const int dxi  = s - gidx * 3;
        const int dx   = dxi - 1;

        CP_WAIT0();            // A(gidx) + B(s) resident
        __syncthreads();

        // issue next copies BEFORE the MMA burst (targets are idle buffers)
        if (s < 17) {
            issueB(s + 1);
            if (dxi == 0 && gidx < 5) issueA(gidx + 1);
            CP_COMMIT();
        }

        const float* sAb = s_A + (gidx & 1) * (32 * A_STR);
        const float* sBb = s_B + (s & 1) * (16 * B_STR);
        const int colbase = w * 64 + g + dx + 4;

        #pragma unroll
        for (int ks = 0; ks < 4; ks++) {
            const float* aRow0 = sAb + (ks * 8 + tig) * A_STR + colbase;
            const float* aRow4 = aRow0 + 4 * A_STR;
            uint32_t a[4][4];
            #pragma unroll
            for (int mt = 0; mt < 4; mt++) {
                a[mt][0] = __float_as_uint(aRow0[mt * 16]);
                a[mt][1] = __float_as_uint(aRow0[mt * 16 + 8]);
                a[mt][2] = __float_as_uint(aRow4[mt * 16]);
                a[mt][3] = __float_as_uint(aRow4[mt * 16 + 8]);
            }
            const float* bRow = sBb + (ks * 4 + tig) * B_STR;
            #pragma unroll
            for (int nt = 0; nt < 8; nt++) {
                float2 bv = *(const float2*)(bRow + 2 * (nt * 8 + g));
                const uint32_t b0 = __float_as_uint(bv.x), b1 = __float_as_uint(bv.y);
                #pragma unroll
                for (int mt = 0; mt < 4; mt++)
                    mma_tf32(acc[mt][nt][0], acc[mt][nt][1], acc[mt][nt][2], acc[mt][nt][3],
                             a[mt][0], a[mt][1], a[mt][2], a[mt][3], b0, b1);
            }
        }
    }

    // ---- epilogue ----
    const size_t obase = ((size_t)b << 22) + (size_t)y * 256;
    #pragma unroll
    for (int nt = 0; nt < 8; nt++) {
        const int o0 = nt * 8 + 2 * tig;
        const float bias0 = s_bias[o0], bias1 = s_bias[o0 + 1];
        #pragma unroll
        for (int mt = 0; mt < 4; mt++) {
            const int m = w * 64 + mt * 16 + g;
            float* p0 = out + obase + ((size_t)o0 << 16) + m;
            float* p1 = out + obase + ((size_t)(o0 + 1) << 16) + m;
            p0[0] = acc[mt][nt][0] + bias0;
            p1[0] = acc[mt][nt][1] + bias1;
            p0[8] = acc[mt][nt][2] + bias0;
            p1[8] = acc[mt][nt][3] + bias1;
        }
    }
}

// ==================== launcher ====================
extern "C" void kernel_launch(void* const* d_in, const int* in_sizes, int n_in,
                              void* d_out, int out_size) {
    const float* x      = (const float*)d_in[0];  // [16,64,256,256]
    const float* fc1_w  = (const float*)d_in[1];  // [17,64]
    const float* fc2_w  = (const float*)d_in[2];  // [4,17]
    const float* fc2_b  = (const float*)d_in[3];  // [4]
    const float* weight = (const float*)d_in[4];  // [4,64,64,3,3]
    const float* bias_k = (const float*)d_in[5];  // [4,64]
    float* out = (float*)d_out;

    const int smem_bytes = SMEM_FLOATS * 4;
    cudaFuncSetAttribute(conv_kernel, cudaFuncAttributeMaxDynamicSharedMemorySize, smem_bytes);

    pool_kernel<<<1024, 256>>>(x);
    attn_kernel<<<16, 64>>>(fc1_w, fc2_w, fc2_b, bias_k);
    aggw_kernel<<<256, 256>>>(weight);
    conv_kernel<<<dim3(256, 16), 128, smem_bytes>>>(x, out);
}